// round 12
// baseline (speedup 1.0000x reference)
#include <cuda_runtime.h>
#include <math.h>

#define NMAX 50000
#define EMAX 800000
#define GNUM 64
#define EPSV 1e-5f
#define FINF 3.402823466e38f

// ---------------- scratch (device globals; no allocation allowed) ----------------
__device__ __align__(256) float g_A[NMAX * 64];        // c_i = x@Wi^T + pre_b
__device__ __align__(256) float g_B[NMAX * 64];        // x@Wj^T
__device__ __align__(256) float g_aggr[NMAX * 256];    // [mean | min | max | std]
__device__ __align__(256) float g_x1[NMAX * 64];       // ping-pong features
__device__ __align__(256) float g_x2[NMAX * 64];
__device__ __align__(256) float g_scal[NMAX * 2];      // amp, att per node
__device__ __align__(256) int   g_deg[NMAX];
__device__ __align__(256) int   g_off[NMAX + 1];
__device__ __align__(256) int   g_cursor[NMAX];
__device__ __align__(256) int   g_srcs[EMAX];
__device__ __align__(256) int   g_scan[NMAX];
__device__ __align__(256) int   g_blk[64];
__device__ __align__(256) float g_stat[1];             // sum of log(deg+1)
__device__ __align__(256) float g_pool[GNUM * 64];
__device__ __align__(256) float g_cnt[GNUM];

__device__ __forceinline__ const float* sel_in(int sel, const float* ext) {
    return sel == 0 ? ext : (sel == 1 ? (const float*)g_x1 : (const float*)g_x2);
}

// ---------------- setup kernels ----------------
__global__ void k_zero(int n) {
    int i = blockIdx.x * blockDim.x + threadIdx.x;
    if (i < n) { g_deg[i] = 0; g_cursor[i] = 0; }
    if (i < GNUM * 64) g_pool[i] = 0.f;
    if (i < GNUM) g_cnt[i] = 0.f;
    if (i == 0) { g_stat[0] = 0.f; g_off[0] = 0; }
}

__global__ void k_deg(const int* __restrict__ ei, int E) {
    int e = blockIdx.x * blockDim.x + threadIdx.x;
    if (e >= E) return;
    atomicAdd(&g_deg[ei[E + e]], 1);
}

__global__ void k_scan1(int n) {
    __shared__ int sh[1024];
    int i = blockIdx.x * 1024 + threadIdx.x;
    int v = (i < n) ? g_deg[i] : 0;
    sh[threadIdx.x] = v;
    __syncthreads();
    for (int s = 1; s < 1024; s <<= 1) {
        int t = (threadIdx.x >= s) ? sh[threadIdx.x - s] : 0;
        __syncthreads();
        sh[threadIdx.x] += t;
        __syncthreads();
    }
    if (i < n) g_scan[i] = sh[threadIdx.x];
    if (threadIdx.x == 1023 && blockIdx.x < 64) g_blk[blockIdx.x] = sh[1023];
}

__global__ void k_scan2(int nb) {
    if (threadIdx.x == 0 && blockIdx.x == 0) {
        int run = 0;
        if (nb > 64) nb = 64;
        for (int b = 0; b < nb; b++) { int t = g_blk[b]; g_blk[b] = run; run += t; }
    }
}

__global__ void k_scan3(int n) {
    int i = blockIdx.x * 1024 + threadIdx.x;
    if (i < n) g_off[i + 1] = g_scan[i] + g_blk[blockIdx.x];
}

__global__ void k_csr(const int* __restrict__ ei, int E) {
    int e = blockIdx.x * blockDim.x + threadIdx.x;
    if (e >= E) return;
    int s = ei[e], d = ei[E + e];
    int pos = g_off[d] + atomicAdd(&g_cursor[d], 1);
    g_srcs[pos] = s;
}

__global__ void k_stat(int n) {
    int i = blockIdx.x * blockDim.x + threadIdx.x;
    float v = (i < n) ? logf((float)g_deg[i] + 1.f) : 0.f;
#pragma unroll
    for (int s = 16; s; s >>= 1) v += __shfl_down_sync(0xffffffffu, v, s);
    __shared__ float sh[32];
    if ((threadIdx.x & 31) == 0) sh[threadIdx.x >> 5] = v;
    __syncthreads();
    if (threadIdx.x < 32) {
        float t = (threadIdx.x < (blockDim.x >> 5)) ? sh[threadIdx.x] : 0.f;
#pragma unroll
        for (int s = 16; s; s >>= 1) t += __shfl_down_sync(0xffffffffu, t, s);
        if (threadIdx.x == 0) atomicAdd(g_stat, t);
    }
}

// ---------------- pre GEMM: A = x@Wi^T + b, B = x@Wj^T ----------------
// 128 threads: thread owns 1 output; 4 nodes in flight for ILP.
__global__ __launch_bounds__(128) void k_pre(int insel, const float* __restrict__ ext,
                                             const float* __restrict__ W,
                                             const float* __restrict__ bias, int n) {
    const float* x = sel_in(insel, ext);
    __shared__ float4 xs[32][16];
    int tid = threadIdx.x;
    int o = tid & 63, half = tid >> 6;
    const float* wr = W + o * 128 + half * 64;
    float w[64];
#pragma unroll
    for (int d = 0; d < 64; d++) w[d] = __ldg(wr + d);
    float bv = half ? 0.f : __ldg(bias + o);
    int n0 = blockIdx.x * 32;
#pragma unroll
    for (int i = tid; i < 512; i += 128) {
        int r = i >> 4, c = i & 15, node = n0 + r;
        xs[r][c] = (node < n) ? ((const float4*)x)[node * 16 + c] : make_float4(0.f, 0.f, 0.f, 0.f);
    }
    __syncthreads();
    float* dst = half ? g_B : g_A;
#pragma unroll
    for (int nb4 = 0; nb4 < 32; nb4 += 4) {
        float a0 = bv, a1 = bv, a2 = bv, a3 = bv;
#pragma unroll
        for (int c = 0; c < 16; c++) {
            float4 v0 = xs[nb4 + 0][c];
            float4 v1 = xs[nb4 + 1][c];
            float4 v2 = xs[nb4 + 2][c];
            float4 v3 = xs[nb4 + 3][c];
            float w0 = w[4 * c + 0], w1 = w[4 * c + 1], w2 = w[4 * c + 2], w3 = w[4 * c + 3];
            a0 = fmaf(w0, v0.x, a0); a0 = fmaf(w1, v0.y, a0); a0 = fmaf(w2, v0.z, a0); a0 = fmaf(w3, v0.w, a0);
            a1 = fmaf(w0, v1.x, a1); a1 = fmaf(w1, v1.y, a1); a1 = fmaf(w2, v1.z, a1); a1 = fmaf(w3, v1.w, a1);
            a2 = fmaf(w0, v2.x, a2); a2 = fmaf(w1, v2.y, a2); a2 = fmaf(w2, v2.z, a2); a2 = fmaf(w3, v2.w, a2);
            a3 = fmaf(w0, v3.x, a3); a3 = fmaf(w1, v3.y, a3); a3 = fmaf(w2, v3.z, a3); a3 = fmaf(w3, v3.w, a3);
        }
        if (n0 + nb4 + 0 < n) dst[(n0 + nb4 + 0) * 64 + o] = a0;
        if (n0 + nb4 + 1 < n) dst[(n0 + nb4 + 1) * 64 + o] = a1;
        if (n0 + nb4 + 2 < n) dst[(n0 + nb4 + 2) * 64 + o] = a2;
        if (n0 + nb4 + 3 < n) dst[(n0 + nb4 + 3) * 64 + o] = a3;
    }
}

// ---------------- aggregation: warp per node over CSR ----------------
__global__ __launch_bounds__(256) void k_aggr(int n) {
    int warp = (blockIdx.x * blockDim.x + threadIdx.x) >> 5;
    int lane = threadIdx.x & 31;
    if (warp >= n) return;
    int s = g_off[warp], e = g_off[warp + 1];
    const float2* B2 = (const float2*)g_B;
    float sx = 0.f, sy = 0.f, qx = 0.f, qy = 0.f;
    float mnx = FINF, mny = FINF, mxx = -FINF, mxy = -FINF;
    int i = s;
    for (; i + 4 <= e; i += 4) {
        int a0 = g_srcs[i], a1 = g_srcs[i + 1], a2 = g_srcs[i + 2], a3 = g_srcs[i + 3];
        float2 v0 = B2[a0 * 32 + lane];
        float2 v1 = B2[a1 * 32 + lane];
        float2 v2 = B2[a2 * 32 + lane];
        float2 v3 = B2[a3 * 32 + lane];
        sx += v0.x; sy += v0.y; qx = fmaf(v0.x, v0.x, qx); qy = fmaf(v0.y, v0.y, qy);
        mnx = fminf(mnx, v0.x); mny = fminf(mny, v0.y); mxx = fmaxf(mxx, v0.x); mxy = fmaxf(mxy, v0.y);
        sx += v1.x; sy += v1.y; qx = fmaf(v1.x, v1.x, qx); qy = fmaf(v1.y, v1.y, qy);
        mnx = fminf(mnx, v1.x); mny = fminf(mny, v1.y); mxx = fmaxf(mxx, v1.x); mxy = fmaxf(mxy, v1.y);
        sx += v2.x; sy += v2.y; qx = fmaf(v2.x, v2.x, qx); qy = fmaf(v2.y, v2.y, qy);
        mnx = fminf(mnx, v2.x); mny = fminf(mny, v2.y); mxx = fmaxf(mxx, v2.x); mxy = fmaxf(mxy, v2.y);
        sx += v3.x; sy += v3.y; qx = fmaf(v3.x, v3.x, qx); qy = fmaf(v3.y, v3.y, qy);
        mnx = fminf(mnx, v3.x); mny = fminf(mny, v3.y); mxx = fmaxf(mxx, v3.x); mxy = fmaxf(mxy, v3.y);
    }
    for (; i < e; i++) {
        int a = g_srcs[i];
        float2 v = B2[a * 32 + lane];
        sx += v.x; sy += v.y; qx = fmaf(v.x, v.x, qx); qy = fmaf(v.y, v.y, qy);
        mnx = fminf(mnx, v.x); mny = fminf(mny, v.y); mxx = fmaxf(mxx, v.x); mxy = fmaxf(mxy, v.y);
    }
    int d = e - s;
    float df = (float)d;
    float degv = (float)max(d, 1);
    float2 c = ((const float2*)g_A)[warp * 32 + lane];
    float S1x = fmaf(df, c.x, sx), S1y = fmaf(df, c.y, sy);
    float S2x = df * c.x * c.x + 2.f * c.x * sx + qx;
    float S2y = df * c.y * c.y + 2.f * c.y * sy + qy;
    float meanx = S1x / degv, meany = S1y / degv;
    float varx = fmaxf(S2x / degv - meanx * meanx, 0.f);
    float vary = fmaxf(S2y / degv - meany * meany, 0.f);
    float stdx = sqrtf(varx + EPSV), stdy = sqrtf(vary + EPSV);
    float mnvx, mnvy, mxvx, mxvy;
    if (d > 0) { mnvx = c.x + mnx; mnvy = c.y + mny; mxvx = c.x + mxx; mxvy = c.y + mxy; }
    else { mnvx = mnvy = mxvx = mxvy = 0.f; }
    float2* out = (float2*)(g_aggr + warp * 256);
    out[lane]       = make_float2(meanx, meany);
    out[32 + lane]  = make_float2(mnvx, mnvy);
    out[64 + lane]  = make_float2(mxvx, mxvy);
    out[96 + lane]  = make_float2(stdx, stdy);
    if (lane == 0) {
        float avg = g_stat[0] / (float)n;
        float ld = logf(degv + 1.f);
        g_scal[2 * warp] = ld / avg;
        g_scal[2 * warp + 1] = avg / ld;
    }
}

// ---------------- fused post GEMM + lin GEMM + relu (software-pipelined) ----------------
// post: t[128,64] = virt[128,832] @ W^T + b; then x' = relu(t @ LW^T + lb).
// Mainloop pipelined: store prefetched regs -> sync -> issue next chunk's LDGs
// -> FFMA from smem -> sync. Hides the A/W gather latency under compute.
// smem: mainloop [0..6271] (As 32x132, Ws 32x64); wT at [8192..12287];
// epilogue overlays t[128][64] on [0..8191]. Total 12288 floats = 48KB.
__global__ __launch_bounds__(256) void k_postlin(int insel, const float* __restrict__ ext,
                                                 const float* __restrict__ W,
                                                 const float* __restrict__ bias,
                                                 const float* __restrict__ LW,
                                                 const float* __restrict__ lb,
                                                 int outsel, int n) {
    const float* x = sel_in(insel, ext);
    float* xo = (outsel == 1) ? g_x1 : g_x2;
    __shared__ float sm[12288];
    float* As = sm;             // As[k][row] = sm[k*132 + row]
    float* Ws = sm + 4224;      // Ws[k][o]  = Ws[k*64 + o]
    float* wT = sm + 8192;      // wT[k][o]  = LW[o*64 + k]
    int tid = threadIdx.x;
    int tx = tid & 15, ty = tid >> 4;
    int bm = blockIdx.x * 128;

    // preload transposed lin weights (region untouched by mainloop)
#pragma unroll
    for (int i = tid; i < 4096; i += 256) {
        int o = i >> 6, k = i & 63;
        wT[k * 64 + o] = __ldg(LW + o * 64 + k);
    }

    float acc[8][4];
#pragma unroll
    for (int ii = 0; ii < 8; ii++)
#pragma unroll
        for (int jj = 0; jj < 4; jj++) acc[ii][jj] = 0.f;

    // per-thread gather addressing (fixed across chunks)
    const int arow = tid >> 3;          // 0..31 (row within 32-row group)
    const int ac4 = (tid & 7) * 4;      // 0..28
    const int wo = tid & 63, wkk = (tid >> 6) * 8;

    // prefetch registers
    float4 pa[4]; float ps[4]; float4 pwa, pwb;

    // gather chunk k0 into regs
    auto gather = [&](int k0) {
#pragma unroll
        for (int p = 0; p < 4; p++) {
            int row = p * 32 + arow;
            int nn = bm + row;
            float4 v = make_float4(0.f, 0.f, 0.f, 0.f);
            float sc = 1.f;
            if (nn < n) {
                if (k0 < 64) {
                    v = *(const float4*)(x + nn * 64 + k0 + ac4);
                } else {
                    int koff = (k0 < 320) ? (k0 - 64) : ((k0 < 576) ? (k0 - 320) : (k0 - 576));
                    v = *(const float4*)(g_aggr + nn * 256 + koff + ac4);
                    if (k0 >= 320) sc = __ldg(g_scal + 2 * nn + ((k0 < 576) ? 0 : 1));
                }
            }
            pa[p] = v; ps[p] = sc;
        }
        const float* wp = W + wo * 832 + k0 + wkk;
        pwa = __ldg((const float4*)wp);
        pwb = __ldg((const float4*)(wp + 4));
    };

    gather(0);
    for (int k0 = 0; k0 < 832; k0 += 32) {
        // store prefetched chunk to smem
#pragma unroll
        for (int p = 0; p < 4; p++) {
            int row = p * 32 + arow;
            float sc = ps[p];
            As[(ac4 + 0) * 132 + row] = pa[p].x * sc;
            As[(ac4 + 1) * 132 + row] = pa[p].y * sc;
            As[(ac4 + 2) * 132 + row] = pa[p].z * sc;
            As[(ac4 + 3) * 132 + row] = pa[p].w * sc;
        }
        Ws[(wkk + 0) * 64 + wo] = pwa.x;  Ws[(wkk + 1) * 64 + wo] = pwa.y;
        Ws[(wkk + 2) * 64 + wo] = pwa.z;  Ws[(wkk + 3) * 64 + wo] = pwa.w;
        Ws[(wkk + 4) * 64 + wo] = pwb.x;  Ws[(wkk + 5) * 64 + wo] = pwb.y;
        Ws[(wkk + 6) * 64 + wo] = pwb.z;  Ws[(wkk + 7) * 64 + wo] = pwb.w;
        __syncthreads();
        // issue next chunk's global loads; they retire while we FFMA below
        if (k0 + 32 < 832) gather(k0 + 32);
#pragma unroll
        for (int k = 0; k < 32; k++) {
            float4 wv = *(const float4*)&Ws[k * 64 + tx * 4];
            float4 a0 = *(const float4*)&As[k * 132 + ty * 8];
            float4 a1 = *(const float4*)&As[k * 132 + ty * 8 + 4];
            float av[8] = {a0.x, a0.y, a0.z, a0.w, a1.x, a1.y, a1.z, a1.w};
            float wl[4] = {wv.x, wv.y, wv.z, wv.w};
#pragma unroll
            for (int ii = 0; ii < 8; ii++)
#pragma unroll
                for (int jj = 0; jj < 4; jj++)
                    acc[ii][jj] = fmaf(av[ii], wl[jj], acc[ii][jj]);
        }
        __syncthreads();
    }

    // ---- epilogue: t = acc + bias into smem (overlays As/Ws) ----
    float4 bv = __ldg((const float4*)(bias + tx * 4));
#pragma unroll
    for (int ii = 0; ii < 8; ii++) {
        int row = ty * 8 + ii;
        float4 o;
        o.x = acc[ii][0] + bv.x;
        o.y = acc[ii][1] + bv.y;
        o.z = acc[ii][2] + bv.z;
        o.w = acc[ii][3] + bv.w;
        *(float4*)&sm[row * 64 + tx * 4] = o;
    }
    __syncthreads();

    // ---- lin: x' = relu(t @ LW^T + lb); t rows block-local ----
    float a2[8][4];
#pragma unroll
    for (int ii = 0; ii < 8; ii++)
#pragma unroll
        for (int jj = 0; jj < 4; jj++) a2[ii][jj] = 0.f;
#pragma unroll
    for (int k = 0; k < 64; k += 4) {
        float4 w0 = *(const float4*)&wT[(k + 0) * 64 + tx * 4];
        float4 w1 = *(const float4*)&wT[(k + 1) * 64 + tx * 4];
        float4 w2 = *(const float4*)&wT[(k + 2) * 64 + tx * 4];
        float4 w3 = *(const float4*)&wT[(k + 3) * 64 + tx * 4];
#pragma unroll
        for (int ii = 0; ii < 8; ii++) {
            float4 tv = *(const float4*)&sm[(ty * 8 + ii) * 64 + k];
            a2[ii][0] = fmaf(tv.x, w0.x, a2[ii][0]); a2[ii][0] = fmaf(tv.y, w1.x, a2[ii][0]);
            a2[ii][0] = fmaf(tv.z, w2.x, a2[ii][0]); a2[ii][0] = fmaf(tv.w, w3.x, a2[ii][0]);
            a2[ii][1] = fmaf(tv.x, w0.y, a2[ii][1]); a2[ii][1] = fmaf(tv.y, w1.y, a2[ii][1]);
            a2[ii][1] = fmaf(tv.z, w2.y, a2[ii][1]); a2[ii][1] = fmaf(tv.w, w3.y, a2[ii][1]);
            a2[ii][2] = fmaf(tv.x, w0.z, a2[ii][2]); a2[ii][2] = fmaf(tv.y, w1.z, a2[ii][2]);
            a2[ii][2] = fmaf(tv.z, w2.z, a2[ii][2]); a2[ii][2] = fmaf(tv.w, w3.z, a2[ii][2]);
            a2[ii][3] = fmaf(tv.x, w0.w, a2[ii][3]); a2[ii][3] = fmaf(tv.y, w1.w, a2[ii][3]);
            a2[ii][3] = fmaf(tv.z, w2.w, a2[ii][3]); a2[ii][3] = fmaf(tv.w, w3.w, a2[ii][3]);
        }
    }
    float4 lbv = __ldg((const float4*)(lb + tx * 4));
#pragma unroll
    for (int ii = 0; ii < 8; ii++) {
        int nn = bm + ty * 8 + ii;
        if (nn < n) {
            float4 o;
            o.x = fmaxf(a2[ii][0] + lbv.x, 0.f);
            o.y = fmaxf(a2[ii][1] + lbv.y, 0.f);
            o.z = fmaxf(a2[ii][2] + lbv.z, 0.f);
            o.w = fmaxf(a2[ii][3] + lbv.w, 0.f);
            *(float4*)(xo + nn * 64 + tx * 4) = o;
        }
    }
}

// ---------------- pooling: segmented (batch sorted) + final MLP ----------------
__global__ __launch_bounds__(256) void k_pool(const int* __restrict__ batch, int n) {
    int tid = threadIdx.x;
    int d = tid & 63, sub = tid >> 6;
    int base = blockIdx.x * 128 + sub * 32;
    float run = 0.f, runc = 0.f;
    int cur = -1;
    int lim = min(32, n - base);
    for (int j = 0; j < lim; j++) {
        int nn = base + j;
        int g = batch[nn];
        if (g != cur) {
            if (cur >= 0) {
                atomicAdd(&g_pool[cur * 64 + d], run);
                if (d == 0) atomicAdd(&g_cnt[cur], runc);
            }
            run = 0.f; runc = 0.f; cur = g;
        }
        run += g_x1[nn * 64 + d];
        runc += 1.f;
    }
    if (cur >= 0) {
        atomicAdd(&g_pool[cur * 64 + d], run);
        if (d == 0) atomicAdd(&g_cnt[cur], runc);
    }
}

__global__ void k_mlp(const float* __restrict__ w1, const float* __restrict__ b1,
                      const float* __restrict__ w2, const float* __restrict__ b2,
                      float* __restrict__ out) {
    __shared__ float gs[64][65];
    __shared__ float hs[64][65];
    int tid = threadIdx.x;
    for (int i = tid; i < GNUM * 64; i += 128) {
        int g = i >> 6;
        float c = fmaxf(g_cnt[g], 1.f);
        gs[g][i & 63] = g_pool[i] / c;
    }
    __syncthreads();
    for (int i = tid; i < GNUM * 64; i += 128) {
        int g = i >> 6, k = i & 63;
        float acc = b1[k];
#pragma unroll
        for (int d = 0; d < 64; d++) acc = fmaf(gs[g][d], w1[k * 64 + d], acc);
        hs[g][k] = fmaxf(acc, 0.f);
    }
    __syncthreads();
    for (int i = tid; i < GNUM * 16; i += 128) {
        int g = i >> 4, k = i & 15;
        float acc = b2[k];
#pragma unroll
        for (int d = 0; d < 64; d++) acc = fmaf(hs[g][d], w2[k * 64 + d], acc);
        out[i] = acc;
    }
}

// ---------------- launch ----------------
extern "C" void kernel_launch(void* const* d_in, const int* in_sizes, int n_in,
                              void* d_out, int out_size) {
    const float* x      = (const float*)d_in[0];
    const int*   ei     = (const int*)d_in[1];
    const int*   batch  = (const int*)d_in[2];
    const float* pre_w  = (const float*)d_in[3];
    const float* pre_b  = (const float*)d_in[4];
    const float* post_w = (const float*)d_in[5];
    const float* post_b = (const float*)d_in[6];
    const float* lin_w  = (const float*)d_in[7];
    const float* lin_b  = (const float*)d_in[8];
    const float* mlp_w1 = (const float*)d_in[9];
    const float* mlp_b1 = (const float*)d_in[10];
    const float* mlp_w2 = (const float*)d_in[11];
    const float* mlp_b2 = (const float*)d_in[12];
    float* out = (float*)d_out;

    int N = in_sizes[0] / 64;
    int E = in_sizes[1] / 2;
    if (N > NMAX) N = NMAX;
    if (E > EMAX) E = EMAX;

    int nb = (N + 1023) / 1024;

    k_zero<<<(N + 255) / 256, 256>>>(N);
    k_deg<<<(E + 255) / 256, 256>>>(ei, E);
    k_scan1<<<nb, 1024>>>(N);
    k_scan2<<<1, 32>>>(nb);
    k_scan3<<<nb, 1024>>>(N);
    k_csr<<<(E + 255) / 256, 256>>>(ei, E);
    k_stat<<<(N + 255) / 256, 256>>>(N);

    int gpre = (N + 31) / 32;
    int gpost = (N + 127) / 128;
    int gagg = (N * 32 + 255) / 256;

    for (int l = 0; l < 3; l++) {
        int insel = (l == 0) ? 0 : ((l == 1) ? 1 : 2);
        int outsel = (l == 1) ? 2 : 1;
        k_pre<<<gpre, 128>>>(insel, x, pre_w + l * 64 * 128, pre_b + l * 64, N);
        k_aggr<<<gagg, 256>>>(N);
        k_postlin<<<gpost, 256>>>(insel, x, post_w + l * 64 * 832, post_b + l * 64,
                                  lin_w + l * 64 * 64, lin_b + l * 64, outsel, N);
    }

    k_pool<<<((N + 127) / 128), 256>>>(batch, N);
    k_mlp<<<1, 128>>>(mlp_w1, mlp_b1, mlp_w2, mlp_b2, out);
}

// round 15
// speedup vs baseline: 1.2243x; 1.2243x over previous
#include <cuda_runtime.h>
#include <cuda_fp16.h>
#include <mma.h>
#include <math.h>
#include <stdint.h>

using namespace nvcuda;

#define NMAX 50000
#define EMAX 800000
#define GNUM 64
#define EPSV 1e-5f
#define FINF 3.402823466e38f

// ---------------- scratch (device globals; no allocation allowed) ----------------
__device__ __align__(256) float g_A[NMAX * 64];
__device__ __align__(256) float g_B[NMAX * 64];
__device__ __align__(256) float g_aggr[NMAX * 256];
__device__ __align__(256) float g_x1[NMAX * 64];
__device__ __align__(256) float g_x2[NMAX * 64];
__device__ __align__(256) float g_scal[NMAX * 2];
__device__ __align__(256) int   g_deg[NMAX];
__device__ __align__(256) int   g_off[NMAX + 1];
__device__ __align__(256) int   g_cursor[NMAX];
__device__ __align__(256) int   g_srcs[EMAX];
__device__ __align__(256) int   g_scan[NMAX];
__device__ __align__(256) int   g_blk[64];
__device__ __align__(256) float g_stat[1];
__device__ __align__(256) float g_pool[GNUM * 64];
__device__ __align__(256) float g_cnt[GNUM];

__device__ __forceinline__ const float* sel_in(int sel, const float* ext) {
    return sel == 0 ? ext : (sel == 1 ? (const float*)g_x1 : (const float*)g_x2);
}

__device__ __forceinline__ void split2(float v, __half& hi, __half& lo) {
    hi = __float2half_rn(v);
    lo = __float2half_rn(v - __half2float(hi));
}

// ---------------- setup kernels ----------------
__global__ void k_zero(int n) {
    int i = blockIdx.x * blockDim.x + threadIdx.x;
    if (i < n) { g_deg[i] = 0; g_cursor[i] = 0; }
    if (i < GNUM * 64) g_pool[i] = 0.f;
    if (i < GNUM) g_cnt[i] = 0.f;
    if (i == 0) { g_stat[0] = 0.f; g_off[0] = 0; }
}

__global__ void k_deg(const int* __restrict__ ei, int E) {
    int e = blockIdx.x * blockDim.x + threadIdx.x;
    if (e >= E) return;
    atomicAdd(&g_deg[ei[E + e]], 1);
}

__global__ void k_scan1(int n) {
    __shared__ int sh[1024];
    int i = blockIdx.x * 1024 + threadIdx.x;
    int v = (i < n) ? g_deg[i] : 0;
    sh[threadIdx.x] = v;
    __syncthreads();
    for (int s = 1; s < 1024; s <<= 1) {
        int t = (threadIdx.x >= s) ? sh[threadIdx.x - s] : 0;
        __syncthreads();
        sh[threadIdx.x] += t;
        __syncthreads();
    }
    if (i < n) g_scan[i] = sh[threadIdx.x];
    if (threadIdx.x == 1023 && blockIdx.x < 64) g_blk[blockIdx.x] = sh[1023];
}

__global__ void k_scan2(int nb) {
    if (threadIdx.x == 0 && blockIdx.x == 0) {
        int run = 0;
        if (nb > 64) nb = 64;
        for (int b = 0; b < nb; b++) { int t = g_blk[b]; g_blk[b] = run; run += t; }
    }
}

__global__ void k_scan3(int n) {
    int i = blockIdx.x * 1024 + threadIdx.x;
    if (i < n) g_off[i + 1] = g_scan[i] + g_blk[blockIdx.x];
}

__global__ void k_csr(const int* __restrict__ ei, int E) {
    int e = blockIdx.x * blockDim.x + threadIdx.x;
    if (e >= E) return;
    int s = ei[e], d = ei[E + e];
    int pos = g_off[d] + atomicAdd(&g_cursor[d], 1);
    g_srcs[pos] = s;
}

__global__ void k_stat(int n) {
    int i = blockIdx.x * blockDim.x + threadIdx.x;
    float v = (i < n) ? logf((float)g_deg[i] + 1.f) : 0.f;
#pragma unroll
    for (int s = 16; s; s >>= 1) v += __shfl_down_sync(0xffffffffu, v, s);
    __shared__ float sh[32];
    if ((threadIdx.x & 31) == 0) sh[threadIdx.x >> 5] = v;
    __syncthreads();
    if (threadIdx.x < 32) {
        float t = (threadIdx.x < (blockDim.x >> 5)) ? sh[threadIdx.x] : 0.f;
#pragma unroll
        for (int s = 16; s; s >>= 1) t += __shfl_down_sync(0xffffffffu, t, s);
        if (threadIdx.x == 0) atomicAdd(g_stat, t);
    }
}

// ---------------- pre GEMM: A = x@Wi^T + b, B = x@Wj^T ----------------
__global__ __launch_bounds__(128) void k_pre(int insel, const float* __restrict__ ext,
                                             const float* __restrict__ W,
                                             const float* __restrict__ bias, int n) {
    const float* x = sel_in(insel, ext);
    __shared__ float4 xs[32][16];
    int tid = threadIdx.x;
    int o = tid & 63, half_ = tid >> 6;
    const float* wr = W + o * 128 + half_ * 64;
    float w[64];
#pragma unroll
    for (int d = 0; d < 64; d++) w[d] = __ldg(wr + d);
    float bv = half_ ? 0.f : __ldg(bias + o);
    int n0 = blockIdx.x * 32;
#pragma unroll
    for (int i = tid; i < 512; i += 128) {
        int r = i >> 4, c = i & 15, node = n0 + r;
        xs[r][c] = (node < n) ? ((const float4*)x)[node * 16 + c] : make_float4(0.f, 0.f, 0.f, 0.f);
    }
    __syncthreads();
    float* dst = half_ ? g_B : g_A;
#pragma unroll
    for (int nb4 = 0; nb4 < 32; nb4 += 4) {
        float a0 = bv, a1 = bv, a2 = bv, a3 = bv;
#pragma unroll
        for (int c = 0; c < 16; c++) {
            float4 v0 = xs[nb4 + 0][c];
            float4 v1 = xs[nb4 + 1][c];
            float4 v2 = xs[nb4 + 2][c];
            float4 v3 = xs[nb4 + 3][c];
            float w0 = w[4 * c + 0], w1 = w[4 * c + 1], w2 = w[4 * c + 2], w3 = w[4 * c + 3];
            a0 = fmaf(w0, v0.x, a0); a0 = fmaf(w1, v0.y, a0); a0 = fmaf(w2, v0.z, a0); a0 = fmaf(w3, v0.w, a0);
            a1 = fmaf(w0, v1.x, a1); a1 = fmaf(w1, v1.y, a1); a1 = fmaf(w2, v1.z, a1); a1 = fmaf(w3, v1.w, a1);
            a2 = fmaf(w0, v2.x, a2); a2 = fmaf(w1, v2.y, a2); a2 = fmaf(w2, v2.z, a2); a2 = fmaf(w3, v2.w, a2);
            a3 = fmaf(w0, v3.x, a3); a3 = fmaf(w1, v3.y, a3); a3 = fmaf(w2, v3.z, a3); a3 = fmaf(w3, v3.w, a3);
        }
        if (n0 + nb4 + 0 < n) dst[(n0 + nb4 + 0) * 64 + o] = a0;
        if (n0 + nb4 + 1 < n) dst[(n0 + nb4 + 1) * 64 + o] = a1;
        if (n0 + nb4 + 2 < n) dst[(n0 + nb4 + 2) * 64 + o] = a2;
        if (n0 + nb4 + 3 < n) dst[(n0 + nb4 + 3) * 64 + o] = a3;
    }
}

// ---------------- aggregation: warp per node over CSR ----------------
__global__ __launch_bounds__(256) void k_aggr(int n) {
    int warp = (blockIdx.x * blockDim.x + threadIdx.x) >> 5;
    int lane = threadIdx.x & 31;
    if (warp >= n) return;
    int s = g_off[warp], e = g_off[warp + 1];
    const float2* B2 = (const float2*)g_B;
    float sx = 0.f, sy = 0.f, qx = 0.f, qy = 0.f;
    float mnx = FINF, mny = FINF, mxx = -FINF, mxy = -FINF;
    int i = s;
    for (; i + 4 <= e; i += 4) {
        int a0 = g_srcs[i], a1 = g_srcs[i + 1], a2 = g_srcs[i + 2], a3 = g_srcs[i + 3];
        float2 v0 = B2[a0 * 32 + lane];
        float2 v1 = B2[a1 * 32 + lane];
        float2 v2 = B2[a2 * 32 + lane];
        float2 v3 = B2[a3 * 32 + lane];
        sx += v0.x; sy += v0.y; qx = fmaf(v0.x, v0.x, qx); qy = fmaf(v0.y, v0.y, qy);
        mnx = fminf(mnx, v0.x); mny = fminf(mny, v0.y); mxx = fmaxf(mxx, v0.x); mxy = fmaxf(mxy, v0.y);
        sx += v1.x; sy += v1.y; qx = fmaf(v1.x, v1.x, qx); qy = fmaf(v1.y, v1.y, qy);
        mnx = fminf(mnx, v1.x); mny = fminf(mny, v1.y); mxx = fmaxf(mxx, v1.x); mxy = fmaxf(mxy, v1.y);
        sx += v2.x; sy += v2.y; qx = fmaf(v2.x, v2.x, qx); qy = fmaf(v2.y, v2.y, qy);
        mnx = fminf(mnx, v2.x); mny = fminf(mny, v2.y); mxx = fmaxf(mxx, v2.x); mxy = fmaxf(mxy, v2.y);
        sx += v3.x; sy += v3.y; qx = fmaf(v3.x, v3.x, qx); qy = fmaf(v3.y, v3.y, qy);
        mnx = fminf(mnx, v3.x); mny = fminf(mny, v3.y); mxx = fmaxf(mxx, v3.x); mxy = fmaxf(mxy, v3.y);
    }
    for (; i < e; i++) {
        int a = g_srcs[i];
        float2 v = B2[a * 32 + lane];
        sx += v.x; sy += v.y; qx = fmaf(v.x, v.x, qx); qy = fmaf(v.y, v.y, qy);
        mnx = fminf(mnx, v.x); mny = fminf(mny, v.y); mxx = fmaxf(mxx, v.x); mxy = fmaxf(mxy, v.y);
    }
    int d = e - s;
    float df = (float)d;
    float degv = (float)max(d, 1);
    float2 c = ((const float2*)g_A)[warp * 32 + lane];
    float S1x = fmaf(df, c.x, sx), S1y = fmaf(df, c.y, sy);
    float S2x = df * c.x * c.x + 2.f * c.x * sx + qx;
    float S2y = df * c.y * c.y + 2.f * c.y * sy + qy;
    float meanx = S1x / degv, meany = S1y / degv;
    float varx = fmaxf(S2x / degv - meanx * meanx, 0.f);
    float vary = fmaxf(S2y / degv - meany * meany, 0.f);
    float stdx = sqrtf(varx + EPSV), stdy = sqrtf(vary + EPSV);
    float mnvx, mnvy, mxvx, mxvy;
    if (d > 0) { mnvx = c.x + mnx; mnvy = c.y + mny; mxvx = c.x + mxx; mxvy = c.y + mxy; }
    else { mnvx = mnvy = mxvx = mxvy = 0.f; }
    float2* out = (float2*)(g_aggr + warp * 256);
    out[lane]       = make_float2(meanx, meany);
    out[32 + lane]  = make_float2(mnvx, mnvy);
    out[64 + lane]  = make_float2(mxvx, mxvy);
    out[96 + lane]  = make_float2(stdx, stdy);
    if (lane == 0) {
        float avg = g_stat[0] / (float)n;
        float ld = logf(degv + 1.f);
        g_scal[2 * warp] = ld / avg;
        g_scal[2 * warp + 1] = avg / ld;
    }
}

// ---------------- fused post+lin via wmma fp16 split-precision ----------------
// BM=64 rows/block, BN=64, 256 threads (8 warps). Split a=hi+lo, w=hi+lo;
// acc += ahi*whi + ahi*wlo + alo*whi  (dropped lo*lo term ~2e-7).
// Mainloop bounded with #pragma unroll 1 to cap code size / compile time.
__global__ __launch_bounds__(256) void k_postlin(int insel, const float* __restrict__ ext,
                                                 const float* __restrict__ W,
                                                 const float* __restrict__ bias,
                                                 const float* __restrict__ LW,
                                                 const float* __restrict__ lb,
                                                 int outsel, int n) {
    const float* x = sel_in(insel, ext);
    float* xo = (outsel == 1) ? g_x1 : g_x2;
    __shared__ __align__(256) unsigned char smem[36864];
    __half* As_hi = (__half*)(smem);            // [64][40]
    __half* As_lo = (__half*)(smem + 5120);
    __half* Ws_hi = (__half*)(smem + 10240);    // [64][40]
    __half* Ws_lo = (__half*)(smem + 15360);
    __half* lw_hi = (__half*)(smem);            // [64][72] overlay after mainloop
    __half* lw_lo = (__half*)(smem + 9216);
    float*  t32   = (float*)(smem + 20480);     // [64][64]
    __half* t_hi  = (__half*)(smem + 20480);    // overlays t32
    __half* t_lo  = (__half*)(smem + 20480 + 8192);

    int tid = threadIdx.x;
    int w = tid >> 5;
    int mtile = w >> 1;             // 0..3 (16 rows each)
    int nbase = (w & 1) * 32;       // two 16-wide n tiles at nbase, nbase+16
    int bm = blockIdx.x * 64;

    wmma::fragment<wmma::accumulator, 16, 16, 16, float> acc[2];
    wmma::fill_fragment(acc[0], 0.f);
    wmma::fill_fragment(acc[1], 0.f);

    int row = tid >> 2;             // 0..63
    int kq = (tid & 3) * 8;         // 0,8,16,24

#pragma unroll 1
    for (int k0 = 0; k0 < 832; k0 += 32) {
        // ---- gather A chunk 64x32, split hi/lo ----
        {
            int nn = bm + row;
            float4 va = make_float4(0.f, 0.f, 0.f, 0.f);
            float4 vb = make_float4(0.f, 0.f, 0.f, 0.f);
            float sc = 1.f;
            if (nn < n) {
                if (k0 < 64) {
                    const float4* p = (const float4*)(x + nn * 64 + k0 + kq);
                    va = p[0]; vb = p[1];
                } else {
                    int koff = (k0 < 320) ? (k0 - 64) : ((k0 < 576) ? (k0 - 320) : (k0 - 576));
                    const float4* p = (const float4*)(g_aggr + nn * 256 + koff + kq);
                    va = p[0]; vb = p[1];
                    if (k0 >= 320) sc = __ldg(g_scal + 2 * nn + ((k0 < 576) ? 0 : 1));
                }
            }
            float vs[8] = {va.x * sc, va.y * sc, va.z * sc, va.w * sc,
                           vb.x * sc, vb.y * sc, vb.z * sc, vb.w * sc};
#pragma unroll
            for (int j = 0; j < 8; j++) {
                __half h, l; split2(vs[j], h, l);
                As_hi[row * 40 + kq + j] = h;
                As_lo[row * 40 + kq + j] = l;
            }
        }
        // ---- W chunk 64x32 ----
        {
            int o = row;
            const float4* p = (const float4*)(W + o * 832 + k0 + kq);
            float4 va = __ldg(p), vb = __ldg(p + 1);
            float vs[8] = {va.x, va.y, va.z, va.w, vb.x, vb.y, vb.z, vb.w};
#pragma unroll
            for (int j = 0; j < 8; j++) {
                __half h, l; split2(vs[j], h, l);
                Ws_hi[o * 40 + kq + j] = h;
                Ws_lo[o * 40 + kq + j] = l;
            }
        }
        __syncthreads();
        // ---- mma ----
#pragma unroll
        for (int kk = 0; kk < 32; kk += 16) {
            wmma::fragment<wmma::matrix_a, 16, 16, 16, __half, wmma::row_major> a_hi, a_lo;
            wmma::load_matrix_sync(a_hi, As_hi + mtile * 16 * 40 + kk, 40);
            wmma::load_matrix_sync(a_lo, As_lo + mtile * 16 * 40 + kk, 40);
#pragma unroll
            for (int t = 0; t < 2; t++) {
                int n0 = nbase + t * 16;
                wmma::fragment<wmma::matrix_b, 16, 16, 16, __half, wmma::col_major> b_hi, b_lo;
                wmma::load_matrix_sync(b_hi, Ws_hi + n0 * 40 + kk, 40);
                wmma::load_matrix_sync(b_lo, Ws_lo + n0 * 40 + kk, 40);
                wmma::mma_sync(acc[t], a_hi, b_hi, acc[t]);
                wmma::mma_sync(acc[t], a_hi, b_lo, acc[t]);
                wmma::mma_sync(acc[t], a_lo, b_hi, acc[t]);
            }
        }
        __syncthreads();
    }

    // ---- store t (f32) ----
    wmma::store_matrix_sync(t32 + mtile * 16 * 64 + nbase,      acc[0], 64, wmma::mem_row_major);
    wmma::store_matrix_sync(t32 + mtile * 16 * 64 + nbase + 16, acc[1], 64, wmma::mem_row_major);
    __syncthreads();

    // ---- t + bias -> hi/lo (in place over t32); lw split into R1 ----
    {
        int cb = (tid & 3) * 16;
        float tv[16];
        const float4* bp = (const float4*)(bias + cb);
        float4 b0 = __ldg(bp), b1 = __ldg(bp + 1), b2 = __ldg(bp + 2), b3 = __ldg(bp + 3);
        float bb[16] = {b0.x, b0.y, b0.z, b0.w, b1.x, b1.y, b1.z, b1.w,
                        b2.x, b2.y, b2.z, b2.w, b3.x, b3.y, b3.z, b3.w};
#pragma unroll
        for (int j = 0; j < 16; j++) tv[j] = t32[row * 64 + cb + j] + bb[j];
        float lwv[16];
        const float4* lp = (const float4*)(LW + row * 64 + cb);
        float4 l0 = __ldg(lp), l1 = __ldg(lp + 1), l2 = __ldg(lp + 2), l3 = __ldg(lp + 3);
        float ll[16] = {l0.x, l0.y, l0.z, l0.w, l1.x, l1.y, l1.z, l1.w,
                        l2.x, l2.y, l2.z, l2.w, l3.x, l3.y, l3.z, l3.w};
#pragma unroll
        for (int j = 0; j < 16; j++) lwv[j] = ll[j];
        __syncthreads();   // all t32 reads done before overwrite
#pragma unroll
        for (int j = 0; j < 16; j++) {
            __half h, l; split2(tv[j], h, l);
            t_hi[row * 64 + cb + j] = h;
            t_lo[row * 64 + cb + j] = l;
            __half lh, llo; split2(lwv[j], lh, llo);
            lw_hi[row * 72 + cb + j] = lh;
            lw_lo[row * 72 + cb + j] = llo;
        }
    }
    __syncthreads();

    // ---- lin mma ----
    wmma::fragment<wmma::accumulator, 16, 16, 16, float> acc2[2];
    wmma::fill_fragment(acc2[0], 0.f);
    wmma::fill_fragment(acc2[1], 0.f);
#pragma unroll 1
    for (int kt = 0; kt < 64; kt += 16) {
        wmma::fragment<wmma::matrix_a, 16, 16, 16, __half, wmma::row_major> a_hi, a_lo;
        wmma::load_matrix_sync(a_hi, t_hi + mtile * 16 * 64 + kt, 64);
        wmma::load_matrix_sync(a_lo, t_lo + mtile * 16 * 64 + kt, 64);
#pragma unroll
        for (int t = 0; t < 2; t++) {
            int n0 = nbase + t * 16;
            wmma::fragment<wmma::matrix_b, 16, 16, 16, __half, wmma::col_major> b_hi, b_lo;
            wmma::load_matrix_sync(b_hi, lw_hi + n0 * 72 + kt, 72);
            wmma::load_matrix_sync(b_lo, lw_lo + n0 * 72 + kt, 72);
            wmma::mma_sync(acc2[t], a_hi, b_hi, acc2[t]);
            wmma::mma_sync(acc2[t], a_hi, b_lo, acc2[t]);
            wmma::mma_sync(acc2[t], a_lo, b_hi, acc2[t]);
        }
    }
    __syncthreads();   // t_hi/t_lo reads done before t32 overwrite
    wmma::store_matrix_sync(t32 + mtile * 16 * 64 + nbase,      acc2[0], 64, wmma::mem_row_major);
    wmma::store_matrix_sync(t32 + mtile * 16 * 64 + nbase + 16, acc2[1], 64, wmma::mem_row_major);
    __syncthreads();

    // ---- +lb, relu, store ----
    {
        int nn = bm + row;
        if (nn < n) {
            int cb = (tid & 3) * 16;
            const float4* lbp = (const float4*)(lb + cb);
            float4 l0 = __ldg(lbp), l1 = __ldg(lbp + 1), l2 = __ldg(lbp + 2), l3 = __ldg(lbp + 3);
            float lbv[16] = {l0.x, l0.y, l0.z, l0.w, l1.x, l1.y, l1.z, l1.w,
                             l2.x, l2.y, l2.z, l2.w, l3.x, l3.y, l3.z, l3.w};
#pragma unroll
            for (int q = 0; q < 4; q++) {
                float4 o;
                o.x = fmaxf(t32[row * 64 + cb + q * 4 + 0] + lbv[q * 4 + 0], 0.f);
                o.y = fmaxf(t32[row * 64 + cb + q * 4 + 1] + lbv[q * 4 + 1], 0.f);
                o.z = fmaxf(t32[row * 64 + cb + q * 4 + 2] + lbv[q * 4 + 2], 0.f);
                o.w = fmaxf(t32[row * 64 + cb + q * 4 + 3] + lbv[q * 4 + 3], 0.f);
                *(float4*)(xo + nn * 64 + cb + q * 4) = o;
            }
        }
    }
}

// ---------------- pooling: segmented (batch sorted) + final MLP ----------------
__global__ __launch_bounds__(256) void k_pool(const int* __restrict__ batch, int n) {
    int tid = threadIdx.x;
    int d = tid & 63, sub = tid >> 6;
    int base = blockIdx.x * 128 + sub * 32;
    float run = 0.f, runc = 0.f;
    int cur = -1;
    int lim = min(32, n - base);
    for (int j = 0; j < lim; j++) {
        int nn = base + j;
        int g = batch[nn];
        if (g != cur) {
            if (cur >= 0) {
                atomicAdd(&g_pool[cur * 64 + d], run);
                if (d == 0) atomicAdd(&g_cnt[cur], runc);
            }
            run = 0.f; runc = 0.f; cur = g;
        }
        run += g_x1[nn * 64 + d];
        runc += 1.f;
    }
    if (cur >= 0) {
        atomicAdd(&g_pool[cur * 64 + d], run);
        if (d == 0) atomicAdd(&g_cnt[cur], runc);
    }
}

__global__ void k_mlp(const float* __restrict__ w1, const float* __restrict__ b1,
                      const float* __restrict__ w2, const float* __restrict__ b2,
                      float* __restrict__ out) {
    __shared__ float gs[64][65];
    __shared__ float hs[64][65];
    int tid = threadIdx.x;
    for (int i = tid; i < GNUM * 64; i += 128) {
        int g = i >> 6;
        float c = fmaxf(g_cnt[g], 1.f);
        gs[g][i & 63] = g_pool[i] / c;
    }
    __syncthreads();
    for (int i = tid; i < GNUM * 64; i += 128) {
        int g = i >> 6, k = i & 63;
        float acc = b1[k];
#pragma unroll
        for (int d = 0; d < 64; d++) acc = fmaf(gs[g][d], w1[k * 64 + d], acc);
        hs[g][k] = fmaxf(acc, 0.f);
    }
    __syncthreads();
    for (int i = tid; i < GNUM * 16; i += 128) {
        int g = i >> 4, k = i & 15;
        float acc = b2[k];
#pragma unroll
        for (int d = 0; d < 64; d++) acc = fmaf(hs[g][d], w2[k * 64 + d], acc);
        out[i] = acc;
    }
}

// ---------------- launch ----------------
extern "C" void kernel_launch(void* const* d_in, const int* in_sizes, int n_in,
                              void* d_out, int out_size) {
    const float* x      = (const float*)d_in[0];
    const int*   ei     = (const int*)d_in[1];
    const int*   batch  = (const int*)d_in[2];
    const float* pre_w  = (const float*)d_in[3];
    const float* pre_b  = (const float*)d_in[4];
    const float* post_w = (const float*)d_in[5];
    const float* post_b = (const float*)d_in[6];
    const float* lin_w  = (const float*)d_in[7];
    const float* lin_b  = (const float*)d_in[8];
    const float* mlp_w1 = (const float*)d_in[9];
    const float* mlp_b1 = (const float*)d_in[10];
    const float* mlp_w2 = (const float*)d_in[11];
    const float* mlp_b2 = (const float*)d_in[12];
    float* out = (float*)d_out;

    int N = in_sizes[0] / 64;
    int E = in_sizes[1] / 2;
    if (N > NMAX) N = NMAX;
    if (E > EMAX) E = EMAX;

    int nb = (N + 1023) / 1024;

    k_zero<<<(N + 255) / 256, 256>>>(N);
    k_deg<<<(E + 255) / 256, 256>>>(ei, E);
    k_scan1<<<nb, 1024>>>(N);
    k_scan2<<<1, 32>>>(nb);
    k_scan3<<<nb, 1024>>>(N);
    k_csr<<<(E + 255) / 256, 256>>>(ei, E);
    k_stat<<<(N + 255) / 256, 256>>>(N);

    int gpre = (N + 31) / 32;
    int gpost = (N + 63) / 64;
    int gagg = (N * 32 + 255) / 256;

    for (int l = 0; l < 3; l++) {
        int insel = (l == 0) ? 0 : ((l == 1) ? 1 : 2);
        int outsel = (l == 1) ? 2 : 1;
        k_pre<<<gpre, 128>>>(insel, x, pre_w + l * 64 * 128, pre_b + l * 64, N);
        k_aggr<<<gagg, 256>>>(N);
        k_postlin<<<gpost, 256>>>(insel, x, post_w + l * 64 * 832, post_b + l * 64,
                                  lin_w + l * 64 * 64, lin_b + l * 64, outsel, N);
    }

    k_pool<<<((N + 127) / 128), 256>>>(batch, N);
    k_mlp<<<1, 128>>>(mlp_w1, mlp_b1, mlp_w2, mlp_b2, out);
}